// round 7
// baseline (speedup 1.0000x reference)
#include <cuda_runtime.h>

#define M_TOTAL 8192
#define NPT 128
#define NTILES 64
#define RESULT_ELEMS (M_TOTAL * 7)   // 57344
#define THREADS 1024

// global scratch (no device allocations allowed)
__device__ unsigned int g_keys32[M_TOTAL];       // per-tile sorted key hi (score part)
__device__ unsigned int g_keyslo[M_TOTAL];       // per-tile sorted key lo (~index part)
__device__ unsigned long long g_bar = 0;         // grid barrier ticket counter

// dynamic smem: [0:8192) uint sk32, [8192:16384) uint sklo  (64KB)
extern __shared__ unsigned int s_dyn[];

// ---------------------------------------------------------------------------
__global__ void __launch_bounds__(THREADS) fused_nms_kernel(const float* __restrict__ tr,
                                                            const int* __restrict__ tp,
                                                            float* __restrict__ out,
                                                            int writeKeep) {
    const int tile = blockIdx.x;
    const int tid = threadIdx.x;

    unsigned int* sk32 = s_dyn;
    unsigned int* sklo = s_dyn + M_TOTAL;

    __shared__ float s_in[NPT * 7];              // staged raw input rows
    __shared__ unsigned long long s_keyraw[NPT];
    __shared__ float4 s_sbox[NPT];               // sorted class-shifted boxes
    __shared__ float s_area[NPT];                // sorted areas
    __shared__ unsigned int s_validmask[4];      // valid bits (sorted order)
    __shared__ unsigned int s_rownz[4];          // rows with any suppression bit
    __shared__ uint4 s_sup[NPT];                 // suppression bitmask rows
    __shared__ float s_rec[NPT][8];              // sorted output records
    __shared__ unsigned int s_kw[4];             // final keep bitmask
    __shared__ int s_rank[NPT];                  // global ranks (accumulated)

    // ---- phase 0: stage input ----
    {
        const float4* src = (const float4*)(tr + (size_t)tile * NPT * 7);
        float4* dst = (float4*)s_in;
        if (tid < NPT * 7 / 4) dst[tid] = src[tid];
    }
    if (tid < 4) { s_validmask[tid] = 0; s_rownz[tid] = 0; }
    if (tid < NPT) s_rank[tid] = 0;
    __syncthreads();

    // ---- phase 1: transform, publish raw key (t < 128) ----
    const bool active = (tid < NPT);
    float b0, b1, b2, b3, score, labelf, growth, x0, x1c, x2, x3, area;
    unsigned long long mykey = 0;
    int valid = 0;
    if (active) {
        const int g = tile * NPT + tid;
        const float* r = s_in + tid * 7;
        b0 = r[0]; b1 = r[1]; b2 = r[2]; b3 = r[3];
        score = r[4]; labelf = r[5]; growth = r[6];
        const float hs = (float)tp[tile * 4 + 0];  // h_start -> cols 1,3
        const float ws = (float)tp[tile * 4 + 2];  // w_start -> cols 0,2
        b0 = fminf(fmaxf(__fadd_rn(b0, ws), 0.0f), 4096.0f);
        b1 = fminf(fmaxf(__fadd_rn(b1, hs), 0.0f), 4096.0f);
        b2 = fminf(fmaxf(__fadd_rn(b2, ws), 0.0f), 4096.0f);
        b3 = fminf(fmaxf(__fadd_rn(b3, hs), 0.0f), 4096.0f);

        valid = (score > 0.05f) ? 1 : 0;
        const float skey = valid ? score : __fsub_rn(score, 1e9f);
        unsigned int ob = __float_as_uint(skey);
        ob = (ob & 0x80000000u) ? ~ob : (ob | 0x80000000u);  // monotone float->uint
        // descending score, ties ascending global index (stable argsort)
        mykey = ((unsigned long long)ob << 32) | (unsigned int)(~(unsigned int)g);
        s_keyraw[tid] = mykey;

        const float shift = __fmul_rn(labelf, 8192.0f);      // 2*IMAGE_SIZE
        x0  = __fadd_rn(b0, shift);
        x1c = __fadd_rn(b1, shift);
        x2  = __fadd_rn(b2, shift);
        x3  = __fadd_rn(b3, shift);
        area = __fmul_rn(__fsub_rn(x2, x0), __fsub_rn(x3, x1c));
    }
    __syncthreads();

    // ---- phase 2: rank-sort + scatter into sorted arrays ----
    if (active) {
        int rank = 0;
        #pragma unroll 16
        for (int j = 0; j < NPT; j++) rank += (s_keyraw[j] > mykey) ? 1 : 0;

        s_sbox[rank] = make_float4(x0, x1c, x2, x3);
        s_area[rank] = area;
        atomicOr(&s_validmask[rank >> 5], (unsigned int)valid << (rank & 31));
        s_rec[rank][0] = b0; s_rec[rank][1] = b1; s_rec[rank][2] = b2; s_rec[rank][3] = b3;
        s_rec[rank][4] = score; s_rec[rank][5] = labelf; s_rec[rank][6] = growth;

        g_keys32[tile * NPT + rank] = (unsigned int)(mykey >> 32);
        g_keyslo[tile * NPT + rank] = (unsigned int)mykey;
    }
    __syncthreads();   // keys written; both halves may proceed

    if (tid < 512) {
        // ================= SUP SIDE (warps 0-15) =================
        // phase 3: suppression matrix; (row i, 32-col group w), warp-uniform j
        {
            const int i = tid & 127;
            const int w = tid >> 7;               // 0..3
            unsigned int word = 0;
            if (i < (w << 5) + 31) {              // group has some j > i
                const float4 bi = s_sbox[i];
                const float ai = s_area[i];
                #pragma unroll 4
                for (int jj = 0; jj < 32; jj++) {
                    const int j = (w << 5) + jj;  // uniform across warp -> broadcast
                    const float4 bj = s_sbox[j];
                    const float aj = s_area[j];
                    const float ltx = fmaxf(bi.x, bj.x), lty = fmaxf(bi.y, bj.y);
                    const float rbx = fminf(bi.z, bj.z), rby = fminf(bi.w, bj.w);
                    const float wx = fmaxf(__fsub_rn(rbx, ltx), 0.0f);
                    const float wy = fmaxf(__fsub_rn(rby, lty), 0.0f);
                    // inter==0 -> iou==0 exactly (union>0): never suppresses.
                    if ((j > i) && (wx > 0.0f) && (wy > 0.0f)) {
                        const float inter = __fmul_rn(wx, wy);
                        const float uni = __fsub_rn(__fadd_rn(ai, aj), inter);
                        const float iou = __fdiv_rn(inter, __fadd_rn(uni, 1e-8f));
                        if (iou > 0.5f) word |= (1u << jj);
                    }
                }
            }
            ((unsigned int*)&s_sup[i])[w] = word;   // full word owned: plain STS
            const unsigned int nz = __ballot_sync(0xFFFFFFFFu, word != 0);
            if ((tid & 31) == 0 && nz) atomicOr(&s_rownz[(tid >> 5) & 3], nz);
        }
        asm volatile("bar.sync 2, 512;" ::: "memory");

        // phase 4: sparse greedy reduce (single thread)
        if (tid == 0) {
            unsigned int kw[4];
            kw[0] = s_validmask[0]; kw[1] = s_validmask[1];
            kw[2] = s_validmask[2]; kw[3] = s_validmask[3];
            #pragma unroll
            for (int w = 0; w < 4; w++) {
                const unsigned int rz = s_rownz[w];
                unsigned int act = kw[w] & rz;
                while (act) {
                    const int ib = __ffs(act) - 1;
                    const uint4 s = s_sup[w * 32 + ib];
                    kw[0] &= ~s.x; kw[1] &= ~s.y; kw[2] &= ~s.z; kw[3] &= ~s.w;
                    act = kw[w] & rz & (0xFFFFFFFEu << ib);
                }
            }
            s_kw[0] = kw[0]; s_kw[1] = kw[1]; s_kw[2] = kw[2]; s_kw[3] = kw[3];
        }
    } else {
        // ================= RANK SIDE (warps 16-31) =================
        const int tid2 = tid - 512;

        // grid barrier: arrival + poll by one thread of this side
        if (tid2 == 0) {
            unsigned long long ticket;
            asm volatile("atom.release.gpu.add.u64 %0, [%1], %2;"
                         : "=l"(ticket) : "l"(&g_bar), "l"(1ULL) : "memory");
            const unsigned long long target = (ticket / NTILES + 1ULL) * NTILES;
            unsigned long long cur;
            do {
                asm volatile("ld.acquire.gpu.u64 %0, [%1];"
                             : "=l"(cur) : "l"(&g_bar) : "memory");
            } while (cur < target);
        }
        asm volatile("bar.sync 1, 512;" ::: "memory");

        // phase 5: stage all keys into smem (vectorized L2 loads)
        {
            const uint4* s32 = (const uint4*)g_keys32;
            const uint4* slo = (const uint4*)g_keyslo;
            uint4* d32 = (uint4*)sk32;
            uint4* dlo = (uint4*)sklo;
            #pragma unroll
            for (int idx = tid2; idx < M_TOTAL / 4; idx += 512) {
                d32[idx] = __ldcg(s32 + idx);
                dlo[idx] = __ldcg(slo + idx);
            }
        }
        asm volatile("bar.sync 1, 512;" ::: "memory");

        // phase 6: 16-state interleaved 32-bit binary searches + tie walk
        {
            const int e_local = tid2 & 127;
            const int grp = tid2 >> 7;                // 0..3, 16 tiles each
            const unsigned int k32 = sk32[(tile << 7) + e_local];
            const unsigned int klo = sklo[(tile << 7) + e_local];
            const unsigned int* base = sk32 + (grp << 11);   // 16 tiles * 128

            int lo[16];
            #pragma unroll
            for (int t = 0; t < 16; t++) lo[t] = 0;
            #pragma unroll
            for (int half = 64; half >= 1; half >>= 1) {
                #pragma unroll
                for (int t = 0; t < 16; t++) {
                    if (base[(t << 7) + lo[t] + half - 1] > k32) lo[t] += half;
                }
            }
            int partial = 0;
            #pragma unroll
            for (int t = 0; t < 16; t++) {
                int j = lo[t];
                partial += j;
                // tie walk: equal-hi run sorted by lo descending; bigger lo precedes.
                const int tb = (grp << 11) + (t << 7);
                while (j < NPT && sk32[tb + j] == k32) {
                    partial += (sklo[tb + j] > klo) ? 1 : 0;
                    j++;
                }
            }
            atomicAdd(&s_rank[e_local], partial);
        }
    }
    __syncthreads();   // join both sides

    // ---- phase 7: scatter output rows ----
    if (active) {
        const int rank = s_rank[tid];
        const unsigned int kbit = (s_kw[tid >> 5] >> (tid & 31)) & 1u;
        const float keepf = kbit ? 1.0f : 0.0f;
        float* o = out + (size_t)rank * 7;
        o[0] = s_rec[tid][0] * keepf;
        o[1] = s_rec[tid][1] * keepf;
        o[2] = s_rec[tid][2] * keepf;
        o[3] = s_rec[tid][3] * keepf;
        o[4] = s_rec[tid][4] * keepf;
        o[5] = s_rec[tid][5] * keepf;
        o[6] = s_rec[tid][6] * keepf;
        if (writeKeep) out[RESULT_ELEMS + rank] = keepf;
    }
}

// tail zero-fill only for unexpected out_size layouts
__global__ void fill_zero_kernel(float* __restrict__ out, int start, int end) {
    int i = start + blockIdx.x * blockDim.x + threadIdx.x;
    if (i < end) out[i] = 0.0f;
}

// ---------------------------------------------------------------------------
extern "C" void kernel_launch(void* const* d_in, const int* in_sizes, int n_in,
                              void* d_out, int out_size) {
    const float* tr = (const float*)d_in[0];   // tile_results (64,128,7) f32
    const int*   tp = (const int*)d_in[1];     // tile_positions (64,4) i32
    float* out = (float*)d_out;

    static bool attr_set = false;  // host-side config only
    if (!attr_set) {
        cudaFuncSetAttribute(fused_nms_kernel,
                             cudaFuncAttributeMaxDynamicSharedMemorySize,
                             2 * M_TOTAL * (int)sizeof(unsigned int));
        attr_set = true;
    }

    const int writeKeep = (out_size >= RESULT_ELEMS + M_TOTAL) ? 1 : 0;
    const int covered = writeKeep ? (RESULT_ELEMS + M_TOTAL) : RESULT_ELEMS;
    if (out_size > covered) {
        const int tail = out_size - covered;
        fill_zero_kernel<<<(tail + 255) / 256, 256>>>(out, covered, out_size);
    }

    fused_nms_kernel<<<NTILES, THREADS, 2 * M_TOTAL * sizeof(unsigned int)>>>(
        tr, tp, out, writeKeep);
}